// round 9
// baseline (speedup 1.0000x reference)
#include <cuda_runtime.h>
#include <cuda_fp16.h>
#include <cstdint>

// ---------------------------------------------------------------------------
// Problem constants
// ---------------------------------------------------------------------------
#define TOKENS     512
#define DIM_K      8192
#define DIM_N      8192
#define HASH_SIZE  (1 << 22)
#define P_HASH     2038074743LL
#define HASH_RANGE 4193281LL          // HASH_SIZE - 1024 + 1

// GEMM: CTA tile 128(M) x 128(N) x 64(K-stage); 128 stages; 2 CTAs/SM
#define NSTG    128
#define THREADS 128
#define PIPE    3

// smem: A stage 128 rows x 128B = 16384; B stage 64 rows x 256B = 16384
#define OFF_A(s)   ((s) * 16384)
#define OFF_B(s)   (PIPE * 16384 + (s) * 16384)
#define SMEM_TOTAL (PIPE * 32768)     // 96 KB -> 2 CTAs/SM

// Scratch: x as fp16 [M][K]; W materialized fp16 in TILE-CONTIGUOUS layout:
//   g_wt[kt][nt][k][n], each 32x32 tile = 1024 halves (2 KB) contiguous.
__device__ __half g_xh[TOKENS * DIM_K];          // 8 MB
__device__ __half g_wt[(size_t)DIM_K * DIM_N];   // 128 MB

// ---------------------------------------------------------------------------
// Helpers
// ---------------------------------------------------------------------------
__device__ __forceinline__ uint32_t smem_to_u32(const void* p) {
    uint32_t a;
    asm("{ .reg .u64 t; cvta.to.shared.u64 t, %1; cvt.u32.u64 %0, t; }" : "=r"(a) : "l"(p));
    return a;
}
__device__ __forceinline__ void cp_async_16(uint32_t smem_dst, const void* gmem_src) {
    asm volatile("cp.async.cg.shared.global [%0], [%1], 16;\n" :: "r"(smem_dst), "l"(gmem_src));
}
__device__ __forceinline__ void cp_async_commit() { asm volatile("cp.async.commit_group;\n"); }
template <int N>
__device__ __forceinline__ void cp_async_wait() { asm volatile("cp.async.wait_group %0;\n" :: "n"(N)); }

__device__ __forceinline__ void ldsm_x4(uint32_t (&r)[4], uint32_t addr) {
    asm volatile("ldmatrix.sync.aligned.m8n8.x4.shared.b16 {%0,%1,%2,%3}, [%4];"
                 : "=r"(r[0]), "=r"(r[1]), "=r"(r[2]), "=r"(r[3]) : "r"(addr));
}
__device__ __forceinline__ void ldsm_x4_t(uint32_t (&r)[4], uint32_t addr) {
    asm volatile("ldmatrix.sync.aligned.m8n8.x4.trans.shared.b16 {%0,%1,%2,%3}, [%4];"
                 : "=r"(r[0]), "=r"(r[1]), "=r"(r[2]), "=r"(r[3]) : "r"(addr));
}
__device__ __forceinline__ void mma_f16(float (&c)[4], const uint32_t (&a)[4],
                                        uint32_t b0, uint32_t b1) {
    asm volatile("mma.sync.aligned.m16n8k16.row.col.f32.f16.f16.f32 "
                 "{%0,%1,%2,%3}, {%4,%5,%6,%7}, {%8,%9}, {%0,%1,%2,%3};"
                 : "+f"(c[0]), "+f"(c[1]), "+f"(c[2]), "+f"(c[3])
                 : "r"(a[0]), "r"(a[1]), "r"(a[2]), "r"(a[3]), "r"(b0), "r"(b1));
}

// Robust random_numbers decode (int64 vs int32 storage; values < 2^31)
__device__ __forceinline__ void decode_rn(const int* p,
                                          long long& R1, long long& R2, long long& R3) {
    if (p[1] == 0) { R1 = (unsigned)p[2]; R2 = (unsigned)p[4]; R3 = (unsigned)p[6]; }
    else           { R1 = (unsigned)p[1]; R2 = (unsigned)p[2]; R3 = (unsigned)p[3]; }
}

// ---------------------------------------------------------------------------
// Prep kernel: W hash-gather -> fp16 tile-contiguous; x -> fp16.
//   blocks [0, 65536): one 32x32 tile; thread writes 8 contiguous halves (16B)
//   blocks [65536, +2048): x conversion (512 float4 each)
// ---------------------------------------------------------------------------
#define NTILES (256 * 256)
#define XBLKS  2048

__global__ __launch_bounds__(128)
void prep_kernel(const float* __restrict__ hw,
                 const float* __restrict__ x,
                 const int* __restrict__ rn) {
    const int bid = blockIdx.x;
    const int tid = threadIdx.x;
    if (bid < NTILES) {
        const int kt = bid >> 8, nt = bid & 255;
        long long R1, R2, R3;
        decode_rn(rn, R1, R2, R3);
        long long v = ((long long)kt * R3 + (long long)nt * R2 + R1) % P_HASH;
        const int S = (int)(v % HASH_RANGE);
        const float* src = hw + S + tid * 8;
        __half h[8];
#pragma unroll
        for (int j = 0; j < 8; j++) h[j] = __float2half_rn(src[j]);
        *(uint4*)(g_wt + (size_t)bid * 1024 + tid * 8) = *(const uint4*)h;
    } else {
        const int xb = bid - NTILES;
        const float4* src = (const float4*)x + (size_t)xb * 512;
        __half2* dst = (__half2*)g_xh + (size_t)xb * 1024;
#pragma unroll
        for (int j = 0; j < 4; j++) {
            const int i = tid + j * 128;
            const float4 v = src[i];
            dst[i * 2]     = __floats2half2_rn(v.x, v.y);
            dst[i * 2 + 1] = __floats2half2_rn(v.z, v.w);
        }
    }
}

// ---------------------------------------------------------------------------
// GEMM kernel: fp16 HMMA. 4 warps (2x2), warp tile 64x64 -> 2x fragment
// duplication both operands (96KB smem traffic/stage vs 128KB at 2x4).
//   A smem: [m 128][k 64 halves] rows 128B, chunk swizzle c^(m&7)
//   B smem: [k 64][n 128 halves] rows 256B, chunk swizzle c^(k&7)
// ---------------------------------------------------------------------------
__global__ __launch_bounds__(THREADS, 2)
void rz_f16_kernel(const float* __restrict__ bias,
                   float* __restrict__ out) {
    extern __shared__ char smem[];
    const uint32_t smem_base = smem_to_u32(smem);
    const int tid  = threadIdx.x;
    const int lane = tid & 31;
    const int wid  = tid >> 5;         // 0..3
    const int wm   = wid >> 1;         // 0..1
    const int wn   = wid & 1;          // 0..1
    const int m0   = blockIdx.y * 128;
    const int n0   = blockIdx.x * 128;
    const int nt0  = blockIdx.x * 4;   // first 32-wide n-tile of this CTA

    auto issue = [&](int t) {
        const int slot = t % PIPE;
        const uint32_t As = smem_base + OFF_A(slot);
        const uint32_t Bs = smem_base + OFF_B(slot);
        const __half* xa = g_xh + (size_t)m0 * DIM_K + t * 64;
#pragma unroll
        for (int u = 0; u < 8; u++) {              // A: 1024 16B chunks
            const int ch = tid + u * THREADS;
            const int m = ch >> 3, c = ch & 7;
            cp_async_16(As + m * 128 + ((c ^ (m & 7)) << 4),
                        xa + (size_t)m * DIM_K + c * 8);
        }
        // B: from tile-contiguous g_wt. Stage t covers kt = 2t, 2t+1.
        const __half* wb = g_wt + ((size_t)(t * 2) * 256 + nt0) * 1024;
#pragma unroll
        for (int u = 0; u < 8; u++) {              // 1024 16B chunks
            const int ch = tid + u * THREADS;
            const int k = ch >> 4, c = ch & 15;    // k 0..63, 16B chunk c
            // source: tile (kt_local = k>>5, nt_local = c>>2), elem (k&31, (c&3)*8)
            const size_t srcoff = ((size_t)(k >> 5) * 256 + (c >> 2)) * 1024
                                + (size_t)(k & 31) * 32 + (c & 3) * 8;
            cp_async_16(Bs + k * 256 + ((c ^ (k & 7)) << 4), wb + srcoff);
        }
    };

    float acc[4][8][4];
#pragma unroll
    for (int mt = 0; mt < 4; mt++)
#pragma unroll
        for (int nt = 0; nt < 8; nt++)
#pragma unroll
            for (int j = 0; j < 4; j++) acc[mt][nt][j] = 0.0f;

    issue(0); cp_async_commit();
    issue(1); cp_async_commit();

    // fragment lane addressing (constant across stages)
    const int ar = (lane & 15);            // A row within 16
    const int ac = (lane >> 4);            // A chunk parity
    const int bk = (lane & 7) + ((lane >> 3) & 1) * 8;   // B k within 16
    const int bc = (lane >> 4);            // B n-chunk parity

    for (int t = 0; t < NSTG; t++) {
        cp_async_wait<1>();
        __syncthreads();
        if (t + 2 < NSTG) issue(t + 2);
        cp_async_commit();

        const int slot = t % PIPE;
        const uint32_t As = smem_base + OFF_A(slot);
        const uint32_t Bs = smem_base + OFF_B(slot);
#pragma unroll
        for (int g = 0; g < 4; g++) {
            uint32_t a[4][4];
#pragma unroll
            for (int mt = 0; mt < 4; mt++) {
                const int row = wm * 64 + mt * 16 + ar;
                const int ch  = g * 2 + ac;
                ldsm_x4(a[mt], As + row * 128 + ((ch ^ (row & 7)) << 4));
            }
            uint32_t bf[4][4];
#pragma unroll
            for (int ntp = 0; ntp < 4; ntp++) {
                const int k   = g * 16 + bk;
                const int nch = wn * 8 + ntp * 2 + bc;
                ldsm_x4_t(bf[ntp], Bs + k * 256 + ((nch ^ (k & 7)) << 4));
            }
#pragma unroll
            for (int mt = 0; mt < 4; mt++)
#pragma unroll
                for (int nt = 0; nt < 8; nt++)
                    mma_f16(acc[mt][nt], a[mt],
                            bf[nt >> 1][(nt & 1) * 2], bf[nt >> 1][(nt & 1) * 2 + 1]);
        }
    }

    // Epilogue
#pragma unroll
    for (int mt = 0; mt < 4; mt++) {
#pragma unroll
        for (int nt = 0; nt < 8; nt++) {
            const int m = m0 + wm * 64 + mt * 16 + (lane >> 2);
            const int n = n0 + wn * 64 + nt * 8 + (lane & 3) * 2;
            const float2 b = *(const float2*)&bias[n];
            float2 o0, o1;
            o0.x = acc[mt][nt][0] + b.x;  o0.y = acc[mt][nt][1] + b.y;
            o1.x = acc[mt][nt][2] + b.x;  o1.y = acc[mt][nt][3] + b.y;
            *(float2*)&out[(size_t)m * DIM_N + n]       = o0;
            *(float2*)&out[(size_t)(m + 8) * DIM_N + n] = o1;
        }
    }
}

// ---------------------------------------------------------------------------
// Launch
// ---------------------------------------------------------------------------
extern "C" void kernel_launch(void* const* d_in, const int* in_sizes, int n_in,
                              void* d_out, int out_size) {
    const float* x    = (const float*)d_in[0];
    const float* hw   = (const float*)d_in[1];
    const float* bias = (const float*)d_in[2];
    const int*   rn   = (const int*)d_in[3];
    float*       out  = (float*)d_out;

    prep_kernel<<<NTILES + XBLKS, 128>>>(hw, x, rn);

    cudaFuncSetAttribute(rz_f16_kernel, cudaFuncAttributeMaxDynamicSharedMemorySize, SMEM_TOTAL);
    rz_f16_kernel<<<dim3(DIM_N / 128, TOKENS / 128), THREADS, SMEM_TOTAL>>>(bias, out);
}

// round 10
// speedup vs baseline: 1.1690x; 1.1690x over previous
#include <cuda_runtime.h>
#include <cuda_fp16.h>
#include <cstdint>

// ---------------------------------------------------------------------------
// Problem constants
// ---------------------------------------------------------------------------
#define TOKENS     512
#define DIM_K      8192
#define DIM_N      8192
#define HASH_SIZE  (1 << 22)
#define P_HASH     2038074743LL
#define HASH_RANGE 4193281LL          // HASH_SIZE - 1024 + 1

// GEMM: CTA tile 128(M) x 128(N) x 64(K-stage); 128 stages; 2 CTAs/SM
#define NSTG    128
#define THREADS 256
#define PIPE    3

// smem: A stage 128 rows x 128B = 16384; B stage 64 rows x 256B = 16384
#define OFF_A(s)   ((s) * 16384)
#define OFF_B(s)   (PIPE * 16384 + (s) * 16384)
#define SMEM_TOTAL (PIPE * 32768)     // 96 KB -> 2 CTAs/SM

// Scratch: fp16 copies. W materialized row-major [K][N] (R8 layout).
__device__ __half g_xh[TOKENS * DIM_K];          // 8 MB
__device__ __half g_wh[(size_t)DIM_K * DIM_N];   // 128 MB

// ---------------------------------------------------------------------------
// Helpers
// ---------------------------------------------------------------------------
__device__ __forceinline__ uint32_t smem_to_u32(const void* p) {
    uint32_t a;
    asm("{ .reg .u64 t; cvta.to.shared.u64 t, %1; cvt.u32.u64 %0, t; }" : "=r"(a) : "l"(p));
    return a;
}
__device__ __forceinline__ void cp_async_16(uint32_t smem_dst, const void* gmem_src) {
    asm volatile("cp.async.cg.shared.global [%0], [%1], 16;\n" :: "r"(smem_dst), "l"(gmem_src));
}
__device__ __forceinline__ void cp_async_commit() { asm volatile("cp.async.commit_group;\n"); }
template <int N>
__device__ __forceinline__ void cp_async_wait() { asm volatile("cp.async.wait_group %0;\n" :: "n"(N)); }

__device__ __forceinline__ void ldsm_x4(uint32_t (&r)[4], uint32_t addr) {
    asm volatile("ldmatrix.sync.aligned.m8n8.x4.shared.b16 {%0,%1,%2,%3}, [%4];"
                 : "=r"(r[0]), "=r"(r[1]), "=r"(r[2]), "=r"(r[3]) : "r"(addr));
}
__device__ __forceinline__ void ldsm_x4_t(uint32_t (&r)[4], uint32_t addr) {
    asm volatile("ldmatrix.sync.aligned.m8n8.x4.trans.shared.b16 {%0,%1,%2,%3}, [%4];"
                 : "=r"(r[0]), "=r"(r[1]), "=r"(r[2]), "=r"(r[3]) : "r"(addr));
}
__device__ __forceinline__ void mma_f16(float (&c)[4], const uint32_t (&a)[4],
                                        uint32_t b0, uint32_t b1) {
    asm volatile("mma.sync.aligned.m16n8k16.row.col.f32.f16.f16.f32 "
                 "{%0,%1,%2,%3}, {%4,%5,%6,%7}, {%8,%9}, {%0,%1,%2,%3};"
                 : "+f"(c[0]), "+f"(c[1]), "+f"(c[2]), "+f"(c[3])
                 : "r"(a[0]), "r"(a[1]), "r"(a[2]), "r"(a[3]), "r"(b0), "r"(b1));
}

// Robust random_numbers decode (int64 vs int32 storage; values < 2^31)
__device__ __forceinline__ void decode_rn(const int* p,
                                          long long& R1, long long& R2, long long& R3) {
    if (p[1] == 0) { R1 = (unsigned)p[2]; R2 = (unsigned)p[4]; R3 = (unsigned)p[6]; }
    else           { R1 = (unsigned)p[1]; R2 = (unsigned)p[2]; R3 = (unsigned)p[3]; }
}

// ---------------------------------------------------------------------------
// Prep kernel (identical to R8): W hash-gather -> fp16 row-major; x -> fp16.
// ---------------------------------------------------------------------------
#define NTILES (256 * 256)
#define XBLKS  2048

__global__ __launch_bounds__(128)
void prep_kernel(const float* __restrict__ hw,
                 const float* __restrict__ x,
                 const int* __restrict__ rn) {
    const int bid = blockIdx.x;
    const int tid = threadIdx.x;
    if (bid < NTILES) {
        const int kt = bid >> 8, nt = bid & 255;
        long long R1, R2, R3;
        decode_rn(rn, R1, R2, R3);
        long long v = ((long long)kt * R3 + (long long)nt * R2 + R1) % P_HASH;
        const int S = (int)(v % HASH_RANGE);
        const float* src = hw + S;
        __half* dst = g_wh + (size_t)(kt * 32) * DIM_N + nt * 32;
#pragma unroll
        for (int j = 0; j < 8; j++) {
            const int e = tid + j * 128;          // k*32 + n
            const int k = e >> 5, n = e & 31;
            dst[(size_t)k * DIM_N + n] = __float2half_rn(src[e]);
        }
    } else {
        const int xb = bid - NTILES;
        const float4* src = (const float4*)x + (size_t)xb * 512;
        __half2* dst = (__half2*)g_xh + (size_t)xb * 1024;
#pragma unroll
        for (int j = 0; j < 4; j++) {
            const int i = tid + j * 128;
            const float4 v = src[i];
            dst[i * 2]     = __floats2half2_rn(v.x, v.y);
            dst[i * 2 + 1] = __floats2half2_rn(v.z, v.w);
        }
    }
}

// ---------------------------------------------------------------------------
// GEMM kernel: fp16 HMMA, R8 geometry (8 warps 2x4, warp tile 64x32),
// with software-pipelined B fragments and JIT A fragments.
// ---------------------------------------------------------------------------
__global__ __launch_bounds__(THREADS, 2)
void rz_f16_kernel(const float* __restrict__ bias,
                   float* __restrict__ out) {
    extern __shared__ char smem[];
    const uint32_t smem_base = smem_to_u32(smem);
    const int tid  = threadIdx.x;
    const int lane = tid & 31;
    const int wid  = tid >> 5;         // 0..7
    const int wm   = wid >> 2;         // 0..1
    const int wn   = wid & 3;          // 0..3
    const int m0   = blockIdx.y * 128;
    const int n0   = blockIdx.x * 128;

    auto issue = [&](int t) {
        const int slot = t % PIPE;
        const uint32_t As = smem_base + OFF_A(slot);
        const uint32_t Bs = smem_base + OFF_B(slot);
        const __half* xa = g_xh + (size_t)m0 * DIM_K + t * 64;
        const __half* wb = g_wh + (size_t)(t * 64) * DIM_N + n0;
#pragma unroll
        for (int u = 0; u < 4; u++) {              // A: 1024 16B chunks
            const int ch = tid + u * THREADS;
            const int m = ch >> 3, c = ch & 7;
            cp_async_16(As + m * 128 + ((c ^ (m & 7)) << 4),
                        xa + (size_t)m * DIM_K + c * 8);
        }
#pragma unroll
        for (int u = 0; u < 4; u++) {              // B: 1024 16B chunks
            const int ch = tid + u * THREADS;
            const int k = ch >> 4, c = ch & 15;
            cp_async_16(Bs + k * 256 + ((c ^ (k & 7)) << 4),
                        wb + (size_t)k * DIM_N + c * 8);
        }
        cp_async_commit();
    };

    float acc[4][4][4];
#pragma unroll
    for (int mt = 0; mt < 4; mt++)
#pragma unroll
        for (int nt = 0; nt < 4; nt++)
#pragma unroll
            for (int j = 0; j < 4; j++) acc[mt][nt][j] = 0.0f;

    issue(0);
    issue(1);

    // fragment lane addressing (constant across stages)
    const int ar = (lane & 15);            // A row within 16
    const int ac = (lane >> 4);            // A chunk parity
    const int bk = (lane & 7) + ((lane >> 3) & 1) * 8;   // B k within 16
    const int bc = (lane >> 4);            // B n-chunk parity

    for (int t = 0; t < NSTG; t++) {
        cp_async_wait<1>();
        __syncthreads();

        const int slot = t % PIPE;
        const uint32_t As = smem_base + OFF_A(slot);
        const uint32_t Bs = smem_base + OFF_B(slot);

        // B fragment double buffer across the 4 k-groups
        uint32_t bf[2][2][4];
        uint32_t a[4][4];

        // prefetch g=0 B fragments first (longest dependency chain)
#pragma unroll
        for (int ntp = 0; ntp < 2; ntp++) {
            const int k = bk;                       // g=0
            const int nch = wn * 4 + ntp * 2 + bc;
            ldsm_x4_t(bf[0][ntp], Bs + k * 256 + ((nch ^ (k & 7)) << 4));
        }

#pragma unroll
        for (int g = 0; g < 4; g++) {
            // A fragments for this group
#pragma unroll
            for (int mt = 0; mt < 4; mt++) {
                const int row = wm * 64 + mt * 16 + ar;
                const int ch  = g * 2 + ac;
                ldsm_x4(a[mt], As + row * 128 + ((ch ^ (row & 7)) << 4));
            }
            // overlap the global prefetch burst with g=0's fragment latency
            if (g == 0) { if (t + 2 < NSTG) issue(t + 2); }
            // prefetch next group's B fragments
            if (g < 3) {
#pragma unroll
                for (int ntp = 0; ntp < 2; ntp++) {
                    const int k = (g + 1) * 16 + bk;
                    const int nch = wn * 4 + ntp * 2 + bc;
                    ldsm_x4_t(bf[(g + 1) & 1][ntp],
                              Bs + k * 256 + ((nch ^ (k & 7)) << 4));
                }
            }
            const int cb = g & 1;
#pragma unroll
            for (int mt = 0; mt < 4; mt++)
#pragma unroll
                for (int nt = 0; nt < 4; nt++)
                    mma_f16(acc[mt][nt], a[mt],
                            bf[cb][nt >> 1][(nt & 1) * 2],
                            bf[cb][nt >> 1][(nt & 1) * 2 + 1]);
        }
    }

    // Epilogue
#pragma unroll
    for (int mt = 0; mt < 4; mt++) {
#pragma unroll
        for (int nt = 0; nt < 4; nt++) {
            const int m = m0 + wm * 64 + mt * 16 + (lane >> 2);
            const int n = n0 + wn * 32 + nt * 8 + (lane & 3) * 2;
            const float2 b = *(const float2*)&bias[n];
            float2 o0, o1;
            o0.x = acc[mt][nt][0] + b.x;  o0.y = acc[mt][nt][1] + b.y;
            o1.x = acc[mt][nt][2] + b.x;  o1.y = acc[mt][nt][3] + b.y;
            *(float2*)&out[(size_t)m * DIM_N + n]       = o0;
            *(float2*)&out[(size_t)(m + 8) * DIM_N + n] = o1;
        }
    }
}

// ---------------------------------------------------------------------------
// Launch
// ---------------------------------------------------------------------------
extern "C" void kernel_launch(void* const* d_in, const int* in_sizes, int n_in,
                              void* d_out, int out_size) {
    const float* x    = (const float*)d_in[0];
    const float* hw   = (const float*)d_in[1];
    const float* bias = (const float*)d_in[2];
    const int*   rn   = (const int*)d_in[3];
    float*       out  = (float*)d_out;

    prep_kernel<<<NTILES + XBLKS, 128>>>(hw, x, rn);

    cudaFuncSetAttribute(rz_f16_kernel, cudaFuncAttributeMaxDynamicSharedMemorySize, SMEM_TOTAL);
    rz_f16_kernel<<<dim3(DIM_N / 128, TOKENS / 128), THREADS, SMEM_TOTAL>>>(bias, out);
}